// round 10
// baseline (speedup 1.0000x reference)
#include <cuda_runtime.h>
#include <cuda_bf16.h>
#include <math.h>
#include <stdint.h>

// Problem constants (fixed by reference)
#define BB      2
#define TT      8192
#define EE      256
#define CSZ     128
#define NN      64        // TT / CSZ
#define NSEL    7         // K - 1
#define LEXT    1024      // K * CS
#define EPSF    1e-6f

// score kernel smem geometry
#define LDB     40                    // bf16 row stride of staged [rows][k] tiles
#define TILE_B  (128 * LDB * 2)       // 10240 bytes per tile
#define STG     (4 * TILE_B)          // 40960 bytes per stage (Ah,Al,Bh,Bl)
#define OFF_MAX (2 * STG)             // 81920: float smax[4][128]
#define OFF_PART (OFF_MAX + 4 * 128 * 4)
#define SCORE_SMEM (OFF_PART + 64)

// out kernel smem geometry
#define LDE      136                  // bf16 row stride of [k=32][e=128] B tiles
#define OA_TILE  (128 * LDB * 2)      // 10240: A tile (128 c x 32 l)
#define OB_TILE  (32 * LDE * 2)       // 8704:  B tile (32 l x 128 e)
#define OSTG     (2 * OA_TILE + 2 * OB_TILE)   // 37888 per stage
#define OUT_SMEM (2 * OSTG + 64)

// ---------------------------------------------------------------------------
// Scratch (static device globals — no allocation)
// ---------------------------------------------------------------------------
__device__ __nv_bfloat16 g_hi[(size_t)BB * TT * EE];   // bf16(cn), 8 MB
__device__ __nv_bfloat16 g_lo[(size_t)BB * TT * EE];   // bf16(cn - hi), 8 MB
__device__ __nv_bfloat16 g_xhi[(size_t)BB * TT * EE];  // bf16(x), 8 MB
__device__ __nv_bfloat16 g_xlo[(size_t)BB * TT * EE];  // bf16(x - xhi), 8 MB
__device__ float g_scores[BB * NN * NN];
__device__ int   g_selidx[BB * NN * NSEL];
__device__ float g_selw[BB * NN * NSEL];

// ---------------------------------------------------------------------------
// Base-PTX helpers (no 'a'-target instructions!)
// ---------------------------------------------------------------------------
__device__ __forceinline__ uint32_t smem_u32(const void* p) {
    uint32_t a;
    asm("{ .reg .u64 t; cvta.to.shared.u64 t, %1; cvt.u32.u64 %0, t; }"
        : "=r"(a) : "l"(p));
    return a;
}
__device__ __forceinline__ void cp16(uint32_t dst, const void* src) {
    asm volatile("cp.async.cg.shared.global [%0], [%1], 16;" :: "r"(dst), "l"(src));
}
__device__ __forceinline__ void cp_commit() {
    asm volatile("cp.async.commit_group;" ::: "memory");
}
template<int N> __device__ __forceinline__ void cp_wait() {
    asm volatile("cp.async.wait_group %0;" :: "n"(N) : "memory");
}
__device__ __forceinline__ void ldmx4(uint32_t* r, uint32_t addr) {
    asm volatile("ldmatrix.sync.aligned.m8n8.x4.shared.b16 {%0,%1,%2,%3}, [%4];"
                 : "=r"(r[0]), "=r"(r[1]), "=r"(r[2]), "=r"(r[3]) : "r"(addr));
}
__device__ __forceinline__ void ldmx4t(uint32_t* r, uint32_t addr) {
    asm volatile("ldmatrix.sync.aligned.m8n8.x4.trans.shared.b16 {%0,%1,%2,%3}, [%4];"
                 : "=r"(r[0]), "=r"(r[1]), "=r"(r[2]), "=r"(r[3]) : "r"(addr));
}
__device__ __forceinline__ void mma16816(float* c, const uint32_t* a, const uint32_t* b) {
    asm volatile("mma.sync.aligned.m16n8k16.row.col.f32.bf16.bf16.f32 "
                 "{%0,%1,%2,%3}, {%4,%5,%6,%7}, {%8,%9}, {%0,%1,%2,%3};"
                 : "+f"(c[0]), "+f"(c[1]), "+f"(c[2]), "+f"(c[3])
                 : "r"(a[0]), "r"(a[1]), "r"(a[2]), "r"(a[3]),
                   "r"(b[0]), "r"(b[1]));
}
__device__ __forceinline__ uint32_t pack2(unsigned short a, unsigned short b) {
    return (uint32_t)a | ((uint32_t)b << 16);
}
__device__ __forceinline__ void split_bf16(float f, unsigned short& h, unsigned short& l) {
    __nv_bfloat16 hb = __float2bfloat16(f);
    __nv_bfloat16 lb = __float2bfloat16(f - __bfloat162float(hb));
    h = *reinterpret_cast<unsigned short*>(&hb);
    l = *reinterpret_cast<unsigned short*>(&lb);
}

// ---------------------------------------------------------------------------
// Kernel A: row-normalize + hi/lo bf16 split of cn AND raw x.  One warp/row.
// ---------------------------------------------------------------------------
__global__ __launch_bounds__(256) void normalize_kernel(const float* __restrict__ x) {
    int row  = blockIdx.x * 8 + (threadIdx.x >> 5);
    int lane = threadIdx.x & 31;
    const float4* xr = (const float4*)(x + (size_t)row * EE);
    float4 v0 = xr[lane];
    float4 v1 = xr[lane + 32];
    float ss = v0.x*v0.x + v0.y*v0.y + v0.z*v0.z + v0.w*v0.w
             + v1.x*v1.x + v1.y*v1.y + v1.z*v1.z + v1.w*v1.w;
    #pragma unroll
    for (int off = 16; off; off >>= 1)
        ss += __shfl_xor_sync(0xffffffffu, ss, off);
    float inv = 1.0f / (sqrtf(ss) + EPSF);

    #pragma unroll
    for (int g = 0; g < 2; g++) {
        float4 v = g ? v1 : v0;
        float fr[4] = {v.x, v.y, v.z, v.w};
        unsigned short h[4], l[4], xh[4], xl[4];
        #pragma unroll
        for (int q = 0; q < 4; q++) {
            split_bf16(fr[q] * inv, h[q], l[q]);
            split_bf16(fr[q], xh[q], xl[q]);
        }
        size_t e = (size_t)row * EE + ((size_t)lane + (g ? 32 : 0)) * 4;
        *(uint2*)(g_hi  + e) = make_uint2(pack2(h[0],h[1]),  pack2(h[2],h[3]));
        *(uint2*)(g_lo  + e) = make_uint2(pack2(l[0],l[1]),  pack2(l[2],l[3]));
        *(uint2*)(g_xhi + e) = make_uint2(pack2(xh[0],xh[1]), pack2(xh[2],xh[3]));
        *(uint2*)(g_xlo + e) = make_uint2(pack2(xl[0],xl[1]), pack2(xl[2],xl[3]));
    }
}

// ---------------------------------------------------------------------------
// Kernel B: pair scores via mma.sync bf16 hi/lo (3-product fp32 emulation).
// CTA = (j, i, b), j < i.  C = cn_i @ cn_j^T (128x128x256), score = sum_c max_d C.
// 16 warps in 4(M) x 4(N); each warp computes 32x32 of C.
// ---------------------------------------------------------------------------
__global__ __launch_bounds__(512) void score_kernel() {
    int j = blockIdx.x, i = blockIdx.y, b = blockIdx.z;
    if (j >= i) return;

    extern __shared__ char sm[];
    uint32_t smb = smem_u32(sm);
    int tid = threadIdx.x, lane = tid & 31, wid = tid >> 5;
    int wm = wid & 3, wn = wid >> 2;

    const __nv_bfloat16* srcs[4];
    srcs[0] = g_hi + ((size_t)b * TT + (size_t)i * CSZ) * EE;   // Ah
    srcs[1] = g_lo + ((size_t)b * TT + (size_t)i * CSZ) * EE;   // Al
    srcs[2] = g_hi + ((size_t)b * TT + (size_t)j * CSZ) * EE;   // Bh
    srcs[3] = g_lo + ((size_t)b * TT + (size_t)j * CSZ) * EE;   // Bl

    float acc[2][4][4];
    #pragma unroll
    for (int mf = 0; mf < 2; mf++)
        #pragma unroll
        for (int nf = 0; nf < 4; nf++)
            #pragma unroll
            for (int q = 0; q < 4; q++) acc[mf][nf][q] = 0.0f;

    int g8  = lane & 7, sel = lane >> 3;
    int a_row = g8 + ((sel & 1) ? 8 : 0);
    int a_col = (sel & 2) ? 8 : 0;
    int b_row = g8 + ((sel >= 2) ? 8 : 0);
    int b_col = (sel & 1) ? 8 : 0;

    auto issue_stage = [&](int stage, int kt) {
        uint32_t sbase = smb + stage * STG;
        int k0 = kt * 32;
        #pragma unroll
        for (int t = 0; t < 4; t++) {
            int chunk = tid + t * 512;
            int tile  = chunk >> 9;
            int within = chunk & 511;
            int row = within >> 2;
            int seg = within & 3;
            cp16(sbase + tile * TILE_B + row * (LDB * 2) + seg * 16,
                 srcs[tile] + (size_t)row * EE + k0 + seg * 8);
        }
    };

    issue_stage(0, 0);
    cp_commit();

    for (int kt = 0; kt < 8; kt++) {
        int buf = kt & 1;
        if (kt < 7) {
            issue_stage(buf ^ 1, kt + 1);
            cp_commit();
            cp_wait<1>();
        } else {
            cp_wait<0>();
        }
        __syncthreads();

        uint32_t bAh = smb + buf * STG;
        uint32_t bAl = bAh + TILE_B;
        uint32_t bBh = bAh + 2 * TILE_B;
        uint32_t bBl = bAh + 3 * TILE_B;

        #pragma unroll
        for (int kk = 0; kk < 32; kk += 16) {
            uint32_t aH[2][4], aL[2][4], bH[4][2], bL[4][2];
            #pragma unroll
            for (int mf = 0; mf < 2; mf++) {
                uint32_t off = (uint32_t)((wm * 32 + mf * 16 + a_row) * (LDB * 2)
                                          + (kk + a_col) * 2);
                ldmx4(aH[mf], bAh + off);
                ldmx4(aL[mf], bAl + off);
            }
            #pragma unroll
            for (int p = 0; p < 2; p++) {
                uint32_t off = (uint32_t)((wn * 32 + p * 16 + b_row) * (LDB * 2)
                                          + (kk + b_col) * 2);
                uint32_t r[4];
                ldmx4(r, bBh + off);
                bH[2*p][0] = r[0]; bH[2*p][1] = r[1];
                bH[2*p+1][0] = r[2]; bH[2*p+1][1] = r[3];
                ldmx4(r, bBl + off);
                bL[2*p][0] = r[0]; bL[2*p][1] = r[1];
                bL[2*p+1][0] = r[2]; bL[2*p+1][1] = r[3];
            }
            #pragma unroll
            for (int mf = 0; mf < 2; mf++)
                #pragma unroll
                for (int nf = 0; nf < 4; nf++) {
                    mma16816(acc[mf][nf], aH[mf], bH[nf]);
                    mma16816(acc[mf][nf], aH[mf], bL[nf]);
                    mma16816(acc[mf][nf], aL[mf], bH[nf]);
                }
        }
        __syncthreads();
    }

    // ---- epilogue: score = sum_rows( max_cols C ) ----
    float* smax = (float*)(sm + OFF_MAX);
    #pragma unroll
    for (int mf = 0; mf < 2; mf++)
        #pragma unroll
        for (int h = 0; h < 2; h++) {
            float v = -3.402823466e38f;
            #pragma unroll
            for (int nf = 0; nf < 4; nf++) {
                v = fmaxf(v, acc[mf][nf][2*h]);
                v = fmaxf(v, acc[mf][nf][2*h + 1]);
            }
            v = fmaxf(v, __shfl_xor_sync(0xffffffffu, v, 1));
            v = fmaxf(v, __shfl_xor_sync(0xffffffffu, v, 2));
            if ((lane & 3) == 0)
                smax[wn * 128 + wm * 32 + mf * 16 + h * 8 + (lane >> 2)] = v;
        }
    __syncthreads();

    if (tid < 128) {
        float v = smax[tid];
        v = fmaxf(v, smax[128 + tid]);
        v = fmaxf(v, smax[256 + tid]);
        v = fmaxf(v, smax[384 + tid]);
        float ssum = v;
        #pragma unroll
        for (int off = 16; off; off >>= 1)
            ssum += __shfl_xor_sync(0xffffffffu, ssum, off);
        float* part = (float*)(sm + OFF_PART);
        if (lane == 0) part[wid] = ssum;
    }
    __syncthreads();
    if (tid == 0) {
        float* part = (float*)(sm + OFF_PART);
        g_scores[((size_t)b * NN + i) * NN + j] = part[0] + part[1] + part[2] + part[3];
    }
}

// ---------------------------------------------------------------------------
// Kernel C: top-7, weights, slot arrangement.  One warp per (b, i).
// ---------------------------------------------------------------------------
__global__ void topk_kernel() {
    int bi = blockIdx.x;
    int b = bi / NN, i = bi % NN;
    int lane = threadIdx.x;

    const float* srow = g_scores + ((size_t)b * NN + i) * NN;
    int j0 = lane, j1 = lane + 32;
    float v0 = (j0 < i) ? srow[j0] : -1e9f;
    float v1 = (j1 < i) ? srow[j1] : -1e9f;

    float vals[NSEL]; int idx[NSEL];
    for (int s = 0; s < NSEL; s++) {
        float bv; int bidx;
        if (v0 >= v1) { bv = v0; bidx = j0; } else { bv = v1; bidx = j1; }
        #pragma unroll
        for (int off = 16; off; off >>= 1) {
            float ov = __shfl_xor_sync(0xffffffffu, bv, off);
            int   oi = __shfl_xor_sync(0xffffffffu, bidx, off);
            if (ov > bv || (ov == bv && oi < bidx)) { bv = ov; bidx = oi; }
        }
        vals[s] = bv; idx[s] = bidx;
        if (j0 == bidx) v0 = -3.402823466e38f;
        if (j1 == bidx) v1 = -3.402823466e38f;
    }

    if (lane == 0) {
        int num_sel = (i < NSEL) ? i : NSEL;
        int vs = num_sel - 1;
        if (vs < 0) vs = 0;
        float vmin = vals[vs];
        float w[NSEL];
        for (int s = 0; s < NSEL; s++)
            w[s] = (s < num_sel) ? vals[s] / (vmin + EPSF) : 0.0f;
        int shift = NSEL - i; if (shift < 0) shift = 0;
        for (int t = 0; t < NSEL; t++) {
            int dst = ((size_t)b * NN + i) * NSEL + t;
            if (t >= shift) {
                g_selidx[dst] = idx[t - shift];
                g_selw[dst]   = w[t - shift];
            } else {
                g_selidx[dst] = 0;
                g_selw[dst]   = 0.0f;
            }
        }
    }
}

// ---------------------------------------------------------------------------
// Kernel D: out[b,n] = down_proj @ ext + chunk, via mma.sync bf16 hi/lo.
// CTA = (eh, n, b).  M=128 (c), N=128 (e-half), K=1024 (l).
// 16 warps in 4(M) x 4(N); each warp computes 32x32 of C.
// ---------------------------------------------------------------------------
__global__ __launch_bounds__(512) void out_kernel_mma(const float* __restrict__ x,
                                                      const float* __restrict__ dp,
                                                      float* __restrict__ out) {
    int eh = blockIdx.x, n = blockIdx.y, b = blockIdx.z;

    extern __shared__ char sm[];
    uint32_t smb = smem_u32(sm);
    __shared__ int   s_idx[8];
    __shared__ float s_w[8];

    int tid = threadIdx.x, lane = tid & 31, wid = tid >> 5;
    int wm = wid & 3, wn = wid >> 2;
    int e0 = eh * 128;

    if (tid < NSEL) {
        s_idx[tid] = g_selidx[((size_t)b * NN + n) * NSEL + tid];
        s_w[tid]   = g_selw[((size_t)b * NN + n) * NSEL + tid];
    }
    if (tid == NSEL) { s_idx[NSEL] = n; s_w[NSEL] = 1.0f; }
    __syncthreads();

    const __nv_bfloat16* xhb = g_xhi + (size_t)b * TT * EE;
    const __nv_bfloat16* xlb = g_xlo + (size_t)b * TT * EE;

    // per-thread A staging geometry: 2 float4s (rows of dp)
    int arow[2], acol4[2];
    #pragma unroll
    for (int r = 0; r < 2; r++) {
        int idx = tid + r * 512;
        arow[r]  = idx >> 3;
        acol4[r] = idx & 7;
    }

    auto issue_B = [&](int stage, int kt) {
        uint32_t base = smb + stage * OSTG + 2 * OA_TILE;
        int l0 = kt * 32;
        int slot = l0 >> 7;
        int base_row = s_idx[slot] * CSZ + (l0 & 127);
        #pragma unroll
        for (int t = 0; t < 2; t++) {
            int idx = tid + t * 512;        // 0..1023
            int tile = idx >> 9;            // 0 = hi, 1 = lo
            int within = idx & 511;
            int row = within >> 4;          // 0..31
            int seg = within & 15;          // 16B segment
            const __nv_bfloat16* src = (tile ? xlb : xhb)
                + (size_t)(base_row + row) * EE + e0 + seg * 8;
            cp16(base + tile * OB_TILE + row * (LDE * 2) + seg * 16, src);
        }
    };

    auto store_A = [&](int stage, float4* av, float w) {
        uint32_t offh = stage * OSTG;
        uint32_t offl = offh + OA_TILE;
        #pragma unroll
        for (int r = 0; r < 2; r++) {
            float f[4] = {av[r].x * w, av[r].y * w, av[r].z * w, av[r].w * w};
            unsigned short h[4], l[4];
            #pragma unroll
            for (int q = 0; q < 4; q++) split_bf16(f[q], h[q], l[q]);
            uint32_t off = (uint32_t)(arow[r] * (LDB * 2) + acol4[r] * 8);
            *(uint2*)(sm + offh + off) = make_uint2(pack2(h[0],h[1]), pack2(h[2],h[3]));
            *(uint2*)(sm + offl + off) = make_uint2(pack2(l[0],l[1]), pack2(l[2],l[3]));
        }
    };
    auto fetch_A = [&](float4* av, int kt) {
        int l0 = kt * 32;
        #pragma unroll
        for (int r = 0; r < 2; r++)
            av[r] = *(const float4*)(dp + (size_t)arow[r] * LEXT + l0 + acol4[r] * 4);
    };

    float acc[2][4][4];
    #pragma unroll
    for (int mf = 0; mf < 2; mf++)
        #pragma unroll
        for (int nf = 0; nf < 4; nf++)
            #pragma unroll
            for (int q = 0; q < 4; q++) acc[mf][nf][q] = 0.0f;

    int g8  = lane & 7, sel = lane >> 3;
    int a_row = g8 + ((sel & 1) ? 8 : 0);
    int a_col = (sel & 2) ? 8 : 0;
    int bk_off = g8 + ((sel & 1) ? 8 : 0);   // k offset within chunk (trans)
    int bn_off = (sel & 2) ? 8 : 0;          // n offset

    // prologue: stage kt=0
    {
        float4 av[2];
        fetch_A(av, 0);
        issue_B(0, 0);
        cp_commit();
        store_A(0, av, s_w[0]);
        cp_wait<0>();
        __syncthreads();
    }

    for (int kt = 0; kt < 32; kt++) {
        int buf = kt & 1;
        float4 av[2];
        if (kt < 31) {
            fetch_A(av, kt + 1);
            issue_B(buf ^ 1, kt + 1);
            cp_commit();
        }

        uint32_t bAh = smb + buf * OSTG;
        uint32_t bAl = bAh + OA_TILE;
        uint32_t bBh = bAh + 2 * OA_TILE;
        uint32_t bBl = bBh + OB_TILE;

        #pragma unroll
        for (int kk = 0; kk < 32; kk += 16) {
            uint32_t aH[2][4], aL[2][4], bH[4][2], bL[4][2];
            #pragma unroll
            for (int mf = 0; mf < 2; mf++) {
                uint32_t off = (uint32_t)((wm * 32 + mf * 16 + a_row) * (LDB * 2)
                                          + (kk + a_col) * 2);
                ldmx4(aH[mf], bAh + off);
                ldmx4(aL[mf], bAl + off);
            }
            #pragma unroll
            for (int p = 0; p < 2; p++) {
                uint32_t off = (uint32_t)((kk + bk_off) * (LDE * 2)
                                          + (wn * 32 + p * 16 + bn_off) * 2);
                uint32_t r[4];
                ldmx4t(r, bBh + off);
                bH[2*p][0] = r[0]; bH[2*p][1] = r[1];
                bH[2*p+1][0] = r[2]; bH[2*p+1][1] = r[3];
                ldmx4t(r, bBl + off);
                bL[2*p][0] = r[0]; bL[2*p][1] = r[1];
                bL[2*p+1][0] = r[2]; bL[2*p+1][1] = r[3];
            }
            #pragma unroll
            for (int mf = 0; mf < 2; mf++)
                #pragma unroll
                for (int nf = 0; nf < 4; nf++) {
                    mma16816(acc[mf][nf], aH[mf], bH[nf]);
                    mma16816(acc[mf][nf], aH[mf], bL[nf]);
                    mma16816(acc[mf][nf], aL[mf], bH[nf]);
                }
        }

        if (kt < 31) store_A(buf ^ 1, av, s_w[(kt + 1) >> 2]);
        cp_wait<0>();
        __syncthreads();
    }

    // epilogue: add residual (chunk n) and store
    const float* xb = x + (size_t)b * TT * EE;
    #pragma unroll
    for (int mf = 0; mf < 2; mf++)
        #pragma unroll
        for (int h = 0; h < 2; h++) {
            int row = wm * 32 + mf * 16 + h * 8 + (lane >> 2);
            const float* resrow = xb + ((size_t)n * CSZ + row) * EE + e0;
            float* orow = out + ((size_t)b * TT + (size_t)n * CSZ + row) * EE + e0;
            #pragma unroll
            for (int nf = 0; nf < 4; nf++) {
                int col = wn * 32 + nf * 8 + (lane & 3) * 2;
                float2 res = *(const float2*)(resrow + col);
                float2 o;
                o.x = acc[mf][nf][2*h]     + res.x;
                o.y = acc[mf][nf][2*h + 1] + res.y;
                *(float2*)(orow + col) = o;
            }
        }
}

// ---------------------------------------------------------------------------
extern "C" void kernel_launch(void* const* d_in, const int* in_sizes, int n_in,
                              void* d_out, int out_size) {
    const float* x  = (const float*)d_in[0];
    const float* dp = (const float*)d_in[1];
    if (in_sizes[0] == CSZ * LEXT) {  // down_proj came first
        dp = (const float*)d_in[0];
        x  = (const float*)d_in[1];
    }
    float* out = (float*)d_out;

    cudaFuncSetAttribute(score_kernel,
                         cudaFuncAttributeMaxDynamicSharedMemorySize, SCORE_SMEM);
    cudaFuncSetAttribute(out_kernel_mma,
                         cudaFuncAttributeMaxDynamicSharedMemorySize, OUT_SMEM);

    normalize_kernel<<<(BB * TT) / 8, 256>>>(x);
    score_kernel<<<dim3(NN, NN, BB), 512, SCORE_SMEM>>>();
    topk_kernel<<<BB * NN, 32>>>();
    out_kernel_mma<<<dim3(2, NN, BB), 512, OUT_SMEM>>>(x, dp, out);
}

// round 11
// speedup vs baseline: 1.2309x; 1.2309x over previous
#include <cuda_runtime.h>
#include <cuda_bf16.h>
#include <math.h>
#include <stdint.h>

// Problem constants (fixed by reference)
#define BB      2
#define TT      8192
#define EE      256
#define CSZ     128
#define NN      64        // TT / CSZ
#define NSEL    7         // K - 1
#define LEXT    1024      // K * CS
#define EPSF    1e-6f
#define NPAIR   (NN * (NN - 1) / 2)   // 2016 causal pairs

// score kernel smem geometry
#define LDB     40                    // bf16 row stride of staged [rows][k] tiles
#define TILE_B  (128 * LDB * 2)       // 10240 bytes per tile
#define STG     (4 * TILE_B)          // 40960 bytes per stage (Ah,Al,Bh,Bl)
#define OFF_MAX (2 * STG)             // 81920: float smax[4][128]
#define OFF_PART (OFF_MAX + 4 * 128 * 4)
#define SCORE_SMEM (OFF_PART + 64)

// out kernel smem geometry
#define LDE      136                  // bf16 row stride of [k=32][e=128] B tiles
#define OA_TILE  (128 * LDB * 2)      // 10240: A tile (128 c x 32 l)
#define OB_TILE  (32 * LDE * 2)       // 8704:  B tile (32 l x 128 e)
#define OSTG     (2 * OA_TILE + 2 * OB_TILE)   // 37888 per stage
#define OUT_SMEM (2 * OSTG + 64)

// ---------------------------------------------------------------------------
// Scratch (static device globals — no allocation)
// ---------------------------------------------------------------------------
__device__ __nv_bfloat16 g_hi[(size_t)BB * TT * EE];   // bf16(cn), 8 MB
__device__ __nv_bfloat16 g_lo[(size_t)BB * TT * EE];   // bf16(cn - hi), 8 MB
__device__ __nv_bfloat16 g_xhi[(size_t)BB * TT * EE];  // bf16(x), 8 MB
__device__ __nv_bfloat16 g_xlo[(size_t)BB * TT * EE];  // bf16(x - xhi), 8 MB
__device__ float g_scores[BB * NN * NN];
__device__ int   g_selidx[BB * NN * NSEL];
__device__ float g_selw[BB * NN * NSEL];

// ---------------------------------------------------------------------------
// Base-PTX helpers (no 'a'-target instructions!)
// ---------------------------------------------------------------------------
__device__ __forceinline__ uint32_t smem_u32(const void* p) {
    uint32_t a;
    asm("{ .reg .u64 t; cvta.to.shared.u64 t, %1; cvt.u32.u64 %0, t; }"
        : "=r"(a) : "l"(p));
    return a;
}
__device__ __forceinline__ void cp16(uint32_t dst, const void* src) {
    asm volatile("cp.async.cg.shared.global [%0], [%1], 16;" :: "r"(dst), "l"(src));
}
__device__ __forceinline__ void cp_commit() {
    asm volatile("cp.async.commit_group;" ::: "memory");
}
template<int N> __device__ __forceinline__ void cp_wait() {
    asm volatile("cp.async.wait_group %0;" :: "n"(N) : "memory");
}
__device__ __forceinline__ void ldmx4(uint32_t* r, uint32_t addr) {
    asm volatile("ldmatrix.sync.aligned.m8n8.x4.shared.b16 {%0,%1,%2,%3}, [%4];"
                 : "=r"(r[0]), "=r"(r[1]), "=r"(r[2]), "=r"(r[3]) : "r"(addr));
}
__device__ __forceinline__ void ldmx4t(uint32_t* r, uint32_t addr) {
    asm volatile("ldmatrix.sync.aligned.m8n8.x4.trans.shared.b16 {%0,%1,%2,%3}, [%4];"
                 : "=r"(r[0]), "=r"(r[1]), "=r"(r[2]), "=r"(r[3]) : "r"(addr));
}
__device__ __forceinline__ void mma16816(float* c, const uint32_t* a, const uint32_t* b) {
    asm volatile("mma.sync.aligned.m16n8k16.row.col.f32.bf16.bf16.f32 "
                 "{%0,%1,%2,%3}, {%4,%5,%6,%7}, {%8,%9}, {%0,%1,%2,%3};"
                 : "+f"(c[0]), "+f"(c[1]), "+f"(c[2]), "+f"(c[3])
                 : "r"(a[0]), "r"(a[1]), "r"(a[2]), "r"(a[3]),
                   "r"(b[0]), "r"(b[1]));
}
__device__ __forceinline__ uint32_t pack2(unsigned short a, unsigned short b) {
    return (uint32_t)a | ((uint32_t)b << 16);
}
__device__ __forceinline__ void split_bf16(float f, unsigned short& h, unsigned short& l) {
    __nv_bfloat16 hb = __float2bfloat16(f);
    __nv_bfloat16 lb = __float2bfloat16(f - __bfloat162float(hb));
    h = *reinterpret_cast<unsigned short*>(&hb);
    l = *reinterpret_cast<unsigned short*>(&lb);
}

// ---------------------------------------------------------------------------
// Kernel A: row-normalize + hi/lo bf16 split of cn AND raw x.  One warp/row.
// ---------------------------------------------------------------------------
__global__ __launch_bounds__(256) void normalize_kernel(const float* __restrict__ x) {
    int row  = blockIdx.x * 8 + (threadIdx.x >> 5);
    int lane = threadIdx.x & 31;
    const float4* xr = (const float4*)(x + (size_t)row * EE);
    float4 v0 = xr[lane];
    float4 v1 = xr[lane + 32];
    float ss = v0.x*v0.x + v0.y*v0.y + v0.z*v0.z + v0.w*v0.w
             + v1.x*v1.x + v1.y*v1.y + v1.z*v1.z + v1.w*v1.w;
    #pragma unroll
    for (int off = 16; off; off >>= 1)
        ss += __shfl_xor_sync(0xffffffffu, ss, off);
    float inv = 1.0f / (sqrtf(ss) + EPSF);

    #pragma unroll
    for (int g = 0; g < 2; g++) {
        float4 v = g ? v1 : v0;
        float fr[4] = {v.x, v.y, v.z, v.w};
        unsigned short h[4], l[4], xh[4], xl[4];
        #pragma unroll
        for (int q = 0; q < 4; q++) {
            split_bf16(fr[q] * inv, h[q], l[q]);
            split_bf16(fr[q], xh[q], xl[q]);
        }
        size_t e = (size_t)row * EE + ((size_t)lane + (g ? 32 : 0)) * 4;
        *(uint2*)(g_hi  + e) = make_uint2(pack2(h[0],h[1]),  pack2(h[2],h[3]));
        *(uint2*)(g_lo  + e) = make_uint2(pack2(l[0],l[1]),  pack2(l[2],l[3]));
        *(uint2*)(g_xhi + e) = make_uint2(pack2(xh[0],xh[1]), pack2(xh[2],xh[3]));
        *(uint2*)(g_xlo + e) = make_uint2(pack2(xl[0],xl[1]), pack2(xl[2],xl[3]));
    }
}

// ---------------------------------------------------------------------------
// Kernel B: pair scores via mma.sync bf16 hi/lo (3-product fp32 emulation).
// Triangular grid: blockIdx.x = pair index t -> (i, j), j < i.
// 8 warps in 2(M) x 4(N); each warp computes 64x32 of C.
// ---------------------------------------------------------------------------
__global__ void __launch_bounds__(256, 2) score_kernel() {
    int t = blockIdx.x, b = blockIdx.y;
    int i = (int)((1.0f + sqrtf(1.0f + 8.0f * (float)t)) * 0.5f);
    while (i * (i - 1) / 2 > t) i--;
    while ((i + 1) * i / 2 <= t) i++;
    int j = t - i * (i - 1) / 2;

    extern __shared__ char sm[];
    uint32_t smb = smem_u32(sm);
    int tid = threadIdx.x, lane = tid & 31, wid = tid >> 5;
    int wm = wid & 1, wn = wid >> 1;

    const __nv_bfloat16* srcs[4];
    srcs[0] = g_hi + ((size_t)b * TT + (size_t)i * CSZ) * EE;   // Ah
    srcs[1] = g_lo + ((size_t)b * TT + (size_t)i * CSZ) * EE;   // Al
    srcs[2] = g_hi + ((size_t)b * TT + (size_t)j * CSZ) * EE;   // Bh
    srcs[3] = g_lo + ((size_t)b * TT + (size_t)j * CSZ) * EE;   // Bl

    float acc[4][4][4];
    #pragma unroll
    for (int mf = 0; mf < 4; mf++)
        #pragma unroll
        for (int nf = 0; nf < 4; nf++)
            #pragma unroll
            for (int q = 0; q < 4; q++) acc[mf][nf][q] = 0.0f;

    int g8  = lane & 7, sel = lane >> 3;
    int a_row = g8 + ((sel & 1) ? 8 : 0);
    int a_col = (sel & 2) ? 8 : 0;
    int b_row = g8 + ((sel >= 2) ? 8 : 0);
    int b_col = (sel & 1) ? 8 : 0;

    auto issue_stage = [&](int stage, int kt) {
        uint32_t sbase = smb + stage * STG;
        int k0 = kt * 32;
        #pragma unroll
        for (int tt = 0; tt < 8; tt++) {
            int chunk = tid + tt * 256;
            int tile  = chunk >> 9;
            int within = chunk & 511;
            int row = within >> 2;
            int seg = within & 3;
            cp16(sbase + tile * TILE_B + row * (LDB * 2) + seg * 16,
                 srcs[tile] + (size_t)row * EE + k0 + seg * 8);
        }
    };

    issue_stage(0, 0);
    cp_commit();

    for (int kt = 0; kt < 8; kt++) {
        int buf = kt & 1;
        if (kt < 7) {
            issue_stage(buf ^ 1, kt + 1);
            cp_commit();
            cp_wait<1>();
        } else {
            cp_wait<0>();
        }
        __syncthreads();

        uint32_t bAh = smb + buf * STG;
        uint32_t bAl = bAh + TILE_B;
        uint32_t bBh = bAh + 2 * TILE_B;
        uint32_t bBl = bAh + 3 * TILE_B;

        #pragma unroll
        for (int kk = 0; kk < 32; kk += 16) {
            // B fragments once per kk (16 regs live)
            uint32_t bH[4][2], bL[4][2];
            #pragma unroll
            for (int p = 0; p < 2; p++) {
                uint32_t off = (uint32_t)((wn * 32 + p * 16 + b_row) * (LDB * 2)
                                          + (kk + b_col) * 2);
                uint32_t r[4];
                ldmx4(r, bBh + off);
                bH[2*p][0] = r[0]; bH[2*p][1] = r[1];
                bH[2*p+1][0] = r[2]; bH[2*p+1][1] = r[3];
                ldmx4(r, bBl + off);
                bL[2*p][0] = r[0]; bL[2*p][1] = r[1];
                bL[2*p+1][0] = r[2]; bL[2*p+1][1] = r[3];
            }
            // A fragments per-mf (8 regs live at a time)
            #pragma unroll
            for (int mf = 0; mf < 4; mf++) {
                uint32_t aH[4], aL[4];
                uint32_t off = (uint32_t)((wm * 64 + mf * 16 + a_row) * (LDB * 2)
                                          + (kk + a_col) * 2);
                ldmx4(aH, bAh + off);
                ldmx4(aL, bAl + off);
                #pragma unroll
                for (int nf = 0; nf < 4; nf++) {
                    mma16816(acc[mf][nf], aH, bH[nf]);
                    mma16816(acc[mf][nf], aH, bL[nf]);
                    mma16816(acc[mf][nf], aL, bH[nf]);
                }
            }
        }
        __syncthreads();
    }

    // ---- epilogue: score = sum_rows( max_cols C ) ----
    float* smax = (float*)(sm + OFF_MAX);
    #pragma unroll
    for (int mf = 0; mf < 4; mf++)
        #pragma unroll
        for (int h = 0; h < 2; h++) {
            float v = -3.402823466e38f;
            #pragma unroll
            for (int nf = 0; nf < 4; nf++) {
                v = fmaxf(v, acc[mf][nf][2*h]);
                v = fmaxf(v, acc[mf][nf][2*h + 1]);
            }
            v = fmaxf(v, __shfl_xor_sync(0xffffffffu, v, 1));
            v = fmaxf(v, __shfl_xor_sync(0xffffffffu, v, 2));
            if ((lane & 3) == 0)
                smax[wn * 128 + wm * 64 + mf * 16 + h * 8 + (lane >> 2)] = v;
        }
    __syncthreads();

    if (tid < 128) {
        float v = smax[tid];
        v = fmaxf(v, smax[128 + tid]);
        v = fmaxf(v, smax[256 + tid]);
        v = fmaxf(v, smax[384 + tid]);
        float ssum = v;
        #pragma unroll
        for (int off = 16; off; off >>= 1)
            ssum += __shfl_xor_sync(0xffffffffu, ssum, off);
        float* part = (float*)(sm + OFF_PART);
        if (lane == 0) part[wid] = ssum;
    }
    __syncthreads();
    if (tid == 0) {
        float* part = (float*)(sm + OFF_PART);
        g_scores[((size_t)b * NN + i) * NN + j] = part[0] + part[1] + part[2] + part[3];
    }
}

// ---------------------------------------------------------------------------
// Kernel C: top-7, weights, slot arrangement.  One warp per (b, i).
// ---------------------------------------------------------------------------
__global__ void topk_kernel() {
    int bi = blockIdx.x;
    int b = bi / NN, i = bi % NN;
    int lane = threadIdx.x;

    const float* srow = g_scores + ((size_t)b * NN + i) * NN;
    int j0 = lane, j1 = lane + 32;
    float v0 = (j0 < i) ? srow[j0] : -1e9f;
    float v1 = (j1 < i) ? srow[j1] : -1e9f;

    float vals[NSEL]; int idx[NSEL];
    for (int s = 0; s < NSEL; s++) {
        float bv; int bidx;
        if (v0 >= v1) { bv = v0; bidx = j0; } else { bv = v1; bidx = j1; }
        #pragma unroll
        for (int off = 16; off; off >>= 1) {
            float ov = __shfl_xor_sync(0xffffffffu, bv, off);
            int   oi = __shfl_xor_sync(0xffffffffu, bidx, off);
            if (ov > bv || (ov == bv && oi < bidx)) { bv = ov; bidx = oi; }
        }
        vals[s] = bv; idx[s] = bidx;
        if (j0 == bidx) v0 = -3.402823466e38f;
        if (j1 == bidx) v1 = -3.402823466e38f;
    }

    if (lane == 0) {
        int num_sel = (i < NSEL) ? i : NSEL;
        int vs = num_sel - 1;
        if (vs < 0) vs = 0;
        float vmin = vals[vs];
        float w[NSEL];
        for (int s = 0; s < NSEL; s++)
            w[s] = (s < num_sel) ? vals[s] / (vmin + EPSF) : 0.0f;
        int shift = NSEL - i; if (shift < 0) shift = 0;
        for (int t = 0; t < NSEL; t++) {
            int dst = ((size_t)b * NN + i) * NSEL + t;
            if (t >= shift) {
                g_selidx[dst] = idx[t - shift];
                g_selw[dst]   = w[t - shift];
            } else {
                g_selidx[dst] = 0;
                g_selw[dst]   = 0.0f;
            }
        }
    }
}

// ---------------------------------------------------------------------------
// Kernel D: out[b,n] = down_proj @ ext + chunk, via mma.sync bf16 hi/lo.
// CTA = (eh, n, b).  M=128 (c), N=128 (e-half), K=1024 (l).
// 8 warps in 2(M) x 4(N); each warp computes 64x32 of C.
// ---------------------------------------------------------------------------
__global__ void __launch_bounds__(256, 2) out_kernel_mma(const float* __restrict__ x,
                                                         const float* __restrict__ dp,
                                                         float* __restrict__ out) {
    int eh = blockIdx.x, n = blockIdx.y, b = blockIdx.z;

    extern __shared__ char sm[];
    uint32_t smb = smem_u32(sm);
    __shared__ int   s_idx[8];
    __shared__ float s_w[8];

    int tid = threadIdx.x, lane = tid & 31, wid = tid >> 5;
    int wm = wid & 1, wn = wid >> 1;
    int e0 = eh * 128;

    if (tid < NSEL) {
        s_idx[tid] = g_selidx[((size_t)b * NN + n) * NSEL + tid];
        s_w[tid]   = g_selw[((size_t)b * NN + n) * NSEL + tid];
    }
    if (tid == NSEL) { s_idx[NSEL] = n; s_w[NSEL] = 1.0f; }
    __syncthreads();

    const __nv_bfloat16* xhb = g_xhi + (size_t)b * TT * EE;
    const __nv_bfloat16* xlb = g_xlo + (size_t)b * TT * EE;

    // per-thread A staging geometry: 4 float4s (rows of dp)
    int arow[4], acol4[4];
    #pragma unroll
    for (int r = 0; r < 4; r++) {
        int idx = tid + r * 256;
        arow[r]  = idx >> 3;
        acol4[r] = idx & 7;
    }

    auto issue_B = [&](int stage, int kt) {
        uint32_t base = smb + stage * OSTG + 2 * OA_TILE;
        int l0 = kt * 32;
        int slot = l0 >> 7;
        int base_row = s_idx[slot] * CSZ + (l0 & 127);
        #pragma unroll
        for (int t = 0; t < 4; t++) {
            int idx = tid + t * 256;        // 0..1023
            int tile = idx >> 9;            // 0 = hi, 1 = lo
            int within = idx & 511;
            int row = within >> 4;          // 0..31
            int seg = within & 15;          // 16B segment
            const __nv_bfloat16* src = (tile ? xlb : xhb)
                + (size_t)(base_row + row) * EE + e0 + seg * 8;
            cp16(base + tile * OB_TILE + row * (LDE * 2) + seg * 16, src);
        }
    };

    auto store_A = [&](int stage, float4* av, float w) {
        uint32_t offh = stage * OSTG;
        uint32_t offl = offh + OA_TILE;
        #pragma unroll
        for (int r = 0; r < 4; r++) {
            float f[4] = {av[r].x * w, av[r].y * w, av[r].z * w, av[r].w * w};
            unsigned short h[4], l[4];
            #pragma unroll
            for (int q = 0; q < 4; q++) split_bf16(f[q], h[q], l[q]);
            uint32_t off = (uint32_t)(arow[r] * (LDB * 2) + acol4[r] * 8);
            *(uint2*)(sm + offh + off) = make_uint2(pack2(h[0],h[1]), pack2(h[2],h[3]));
            *(uint2*)(sm + offl + off) = make_uint2(pack2(l[0],l[1]), pack2(l[2],l[3]));
        }
    };
    auto fetch_A = [&](float4* av, int kt) {
        int l0 = kt * 32;
        #pragma unroll
        for (int r = 0; r < 4; r++)
            av[r] = *(const float4*)(dp + (size_t)arow[r] * LEXT + l0 + acol4[r] * 4);
    };

    float acc[4][4][4];
    #pragma unroll
    for (int mf = 0; mf < 4; mf++)
        #pragma unroll
        for (int nf = 0; nf < 4; nf++)
            #pragma unroll
            for (int q = 0; q < 4; q++) acc[mf][nf][q] = 0.0f;

    int g8  = lane & 7, sel = lane >> 3;
    int a_row = g8 + ((sel & 1) ? 8 : 0);
    int a_col = (sel & 2) ? 8 : 0;
    int bk_off = g8 + ((sel & 1) ? 8 : 0);   // k offset within chunk (trans)
    int bn_off = (sel & 2) ? 8 : 0;          // n offset

    // prologue: stage kt=0
    {
        float4 av[4];
        fetch_A(av, 0);
        issue_B(0, 0);
        cp_commit();
        store_A(0, av, s_w[0]);
        cp_wait<0>();
        __syncthreads();
    }

    for (int kt = 0; kt < 32; kt++) {
        int buf = kt & 1;
        float4 av[4];
        if (kt < 31) {
            fetch_A(av, kt + 1);
            issue_B(buf ^ 1, kt + 1);
            cp_commit();
        }

        uint32_t bAh = smb + buf * OSTG;
        uint32_t bAl = bAh + OA_TILE;
        uint32_t bBh = bAh + 2 * OA_TILE;
        uint32_t bBl = bBh + OB_TILE;

        #pragma unroll
        for (int kk = 0; kk < 32; kk += 16) {
            uint32_t bH[4][2], bL[4][2];
            #pragma unroll
            for (int p = 0; p < 2; p++) {
                uint32_t off = (uint32_t)((kk + bk_off) * (LDE * 2)
                                          + (wn * 32 + p * 16 + bn_off) * 2);
                uint32_t r[4];
                ldmx4t(r, bBh + off);
                bH[2*p][0] = r[0]; bH[2*p][1] = r[1];
                bH[2*p+1][0] = r[2]; bH[2*p+1][1] = r[3];
                ldmx4t(r, bBl + off);
                bL[2*p][0] = r[0]; bL[2*p][1] = r[1];
                bL[2*p+1][0] = r[2]; bL[2*p+1][1] = r[3];
            }
            #pragma unroll
            for (int mf = 0; mf < 4; mf++) {
                uint32_t aH[4], aL[4];
                uint32_t off = (uint32_t)((wm * 64 + mf * 16 + a_row) * (LDB * 2)
                                          + (kk + a_col) * 2);
                ldmx4(aH, bAh + off);
                ldmx4(aL, bAl + off);
                #pragma unroll
                for (int nf = 0; nf < 4; nf++) {
                    mma16816(acc[mf][nf], aH, bH[nf]);
                    mma16816(acc[mf][nf], aH, bL[nf]);
                    mma16816(acc[mf][nf], aL, bH[nf]);
                }
            }
        }

        if (kt < 31) store_A(buf ^ 1, av, s_w[(kt + 1) >> 2]);
        cp_wait<0>();
        __syncthreads();
    }

    // epilogue: add residual (chunk n) and store
    const float* xb = x + (size_t)b * TT * EE;
    #pragma unroll
    for (int mf = 0; mf < 4; mf++)
        #pragma unroll
        for (int h = 0; h < 2; h++) {
            int row = wm * 64 + mf * 16 + h * 8 + (lane >> 2);
            const float* resrow = xb + ((size_t)n * CSZ + row) * EE + e0;
            float* orow = out + ((size_t)b * TT + (size_t)n * CSZ + row) * EE + e0;
            #pragma unroll
            for (int nf = 0; nf < 4; nf++) {
                int col = wn * 32 + nf * 8 + (lane & 3) * 2;
                float2 res = *(const float2*)(resrow + col);
                float2 o;
                o.x = acc[mf][nf][2*h]     + res.x;
                o.y = acc[mf][nf][2*h + 1] + res.y;
                *(float2*)(orow + col) = o;
            }
        }
}

// ---------------------------------------------------------------------------
extern "C" void kernel_launch(void* const* d_in, const int* in_sizes, int n_in,
                              void* d_out, int out_size) {
    const float* x  = (const float*)d_in[0];
    const float* dp = (const float*)d_in[1];
    if (in_sizes[0] == CSZ * LEXT) {  // down_proj came first
        dp = (const float*)d_in[0];
        x  = (const float*)d_in[1];
    }
    float* out = (float*)d_out;

    cudaFuncSetAttribute(score_kernel,
                         cudaFuncAttributeMaxDynamicSharedMemorySize, SCORE_SMEM);
    cudaFuncSetAttribute(out_kernel_mma,
                         cudaFuncAttributeMaxDynamicSharedMemorySize, OUT_SMEM);

    normalize_kernel<<<(BB * TT) / 8, 256>>>(x);
    score_kernel<<<dim3(NPAIR, BB), 256, SCORE_SMEM>>>();
    topk_kernel<<<BB * NN, 32>>>();
    out_kernel_mma<<<dim3(2, NN, BB), 256, OUT_SMEM>>>(x, dp, out);
}